// round 8
// baseline (speedup 1.0000x reference)
#include <cuda_runtime.h>

#define N_NODES 100000
#define N_EDGES 1600000
#define IN_CH   128
#define HID_CH  64
#define OUT_CH  40
#define SCAN_B  1024
#define SCAN_NB ((N_NODES + SCAN_B - 1) / SCAN_B)   // 98

typedef unsigned long long ull;

// ---------------- scratch (static device globals; no allocation) ----------------
__device__ float g_h[N_NODES * 64];      // GEMM output of current layer
__device__ float g_a[N_NODES * 64];      // layer-1 aggregated/activated
__device__ float g_b[N_NODES * 64];      // layer-2 aggregated/activated
__device__ float g_dis[N_NODES];         // (deg+1)^-1/2
__device__ int   g_cnt[N_NODES];         // in-degree (excl. self-loop)
__device__ int   g_rs[N_NODES];          // CSR row start
__device__ int   g_cur[N_NODES];         // CSR fill cursors
__device__ int2  g_cw[N_EDGES];          // CSR {src, norm-as-int}
__device__ int   g_bsum[SCAN_NB];        // scan block sums
__device__ float g_w3p[64 * 64];         // W3 zero-padded to 64 cols

static inline int cdiv_i(long long a, int b) { return (int)((a + b - 1) / b); }

// ---------------- packed f32x2 helpers ----------------
__device__ __forceinline__ void ffma2(ull& d, ull a, ull b) {
    asm("fma.rn.f32x2 %0, %1, %2, %0;" : "+l"(d) : "l"(a), "l"(b));
}
__device__ __forceinline__ ull f2u2(float x, float y) {
    ull v; asm("mov.b64 %0, {%1, %2};" : "=l"(v) : "f"(x), "f"(y)); return v;
}
__device__ __forceinline__ float2 u2f2(ull v) {
    float2 f; asm("mov.b64 {%0, %1}, %2;" : "=f"(f.x), "=f"(f.y) : "l"(v)); return f;
}

// ---------------- prep: degree / dis / CSR ----------------
__global__ void cnt_zero_kernel() {
    int i = blockIdx.x * blockDim.x + threadIdx.x;
    if (i < N_NODES) { g_cnt[i] = 0; g_cur[i] = 0; }
}

__global__ void deg_count_kernel(const int* __restrict__ ei) {
    int e = blockIdx.x * blockDim.x + threadIdx.x;
    if (e < N_EDGES) atomicAdd(&g_cnt[ei[N_EDGES + e]], 1);
}

__global__ void dis_kernel() {
    int i = blockIdx.x * blockDim.x + threadIdx.x;
    if (i < N_NODES) g_dis[i] = rsqrtf((float)(g_cnt[i] + 1));  // +1 self-loop
}

// block-level scan (shuffle based): g_rs = exclusive-scan(g_cnt) within block
__global__ void scan_block_kernel() {
    __shared__ int wsum[32];
    int i = blockIdx.x * SCAN_B + threadIdx.x;
    int lane = threadIdx.x & 31, wid = threadIdx.x >> 5;
    int v = (i < N_NODES) ? g_cnt[i] : 0;
    int s = v;
#pragma unroll
    for (int off = 1; off < 32; off <<= 1) {
        int t = __shfl_up_sync(0xffffffffu, s, off);
        if (lane >= off) s += t;
    }
    if (lane == 31) wsum[wid] = s;
    __syncthreads();
    if (wid == 0) {
        int ws = wsum[lane];
#pragma unroll
        for (int off = 1; off < 32; off <<= 1) {
            int t = __shfl_up_sync(0xffffffffu, ws, off);
            if (lane >= off) ws += t;
        }
        wsum[lane] = ws;
    }
    __syncthreads();
    int prefix = (wid > 0) ? wsum[wid - 1] : 0;
    if (i < N_NODES) g_rs[i] = prefix + s - v;  // exclusive
    if (threadIdx.x == SCAN_B - 1) g_bsum[blockIdx.x] = prefix + s;
}

// scan the 98 block sums with one warp (each lane owns 4)
__global__ void scan_sums_kernel() {
    int lane = threadIdx.x;
    int base = lane * 4;
    int v0 = (base + 0 < SCAN_NB) ? g_bsum[base + 0] : 0;
    int v1 = (base + 1 < SCAN_NB) ? g_bsum[base + 1] : 0;
    int v2 = (base + 2 < SCAN_NB) ? g_bsum[base + 2] : 0;
    int v3 = (base + 3 < SCAN_NB) ? g_bsum[base + 3] : 0;
    int tot = v0 + v1 + v2 + v3;
    int s = tot;
#pragma unroll
    for (int off = 1; off < 32; off <<= 1) {
        int t = __shfl_up_sync(0xffffffffu, s, off);
        if (lane >= off) s += t;
    }
    int off0 = s - tot;  // exclusive
    if (base + 0 < SCAN_NB) g_bsum[base + 0] = off0;
    if (base + 1 < SCAN_NB) g_bsum[base + 1] = off0 + v0;
    if (base + 2 < SCAN_NB) g_bsum[base + 2] = off0 + v0 + v1;
    if (base + 3 < SCAN_NB) g_bsum[base + 3] = off0 + v0 + v1 + v2;
}

__global__ void scan_add_kernel() {
    int i = blockIdx.x * SCAN_B + threadIdx.x;
    if (i < N_NODES) g_rs[i] += g_bsum[blockIdx.x];
}

__global__ void fill_csr_kernel(const int* __restrict__ ei) {
    int e = blockIdx.x * blockDim.x + threadIdx.x;
    if (e >= N_EDGES) return;
    int s = ei[e];
    int d = ei[N_EDGES + e];
    int p = g_rs[d] + atomicAdd(&g_cur[d], 1);
    g_cw[p] = make_int2(s, __float_as_int(g_dis[s] * g_dis[d]));
}

__global__ void padw3_kernel(const float* __restrict__ w3) {
    int i = blockIdx.x * blockDim.x + threadIdx.x;
    if (i < 64 * 64) {
        int r = i >> 6, c = i & 63;
        g_w3p[i] = (c < OUT_CH) ? w3[r * OUT_CH + c] : 0.0f;
    }
}

// ---------------- GEMM: H[n][OUTW] = X[n][CIN] @ W[CIN][64]  (f32x2 packed FMA) ----
// SELX: 0 = external, 1 = g_a, 2 = g_b.  SELW: 0 = external, 1 = g_w3p.
// OUTW: 64 = full rows into g_h; 40 = compact rows into g_h (stride 40, cols<40).
template <int CIN, int SELX, int SELW, int OUTW>
__global__ void gemm64_kernel(const float* __restrict__ Xext,
                              const float* __restrict__ Wext, int nrows) {
    __shared__ float Xs[16 * 68];   // [k][row], 272B row stride (16B multiple)
    __shared__ ull   Wd[16 * 64];   // [k][col], each entry = {w, w} duplicated

    const float* X = (SELX == 0) ? Xext : (SELX == 1) ? (const float*)g_a
                                                      : (const float*)g_b;
    const float* W = (SELW == 0) ? Wext : (const float*)g_w3p;
    float* H = g_h;

    const int tid = threadIdx.x;              // 0..127
    const int blockRow = blockIdx.x * 64;
    const int tx = tid & 15, ty = tid >> 4;
    const int col0 = tx * 4, row0 = ty * 8;

    ull acc2[4][4];                           // [row-pair][col], packed {even,odd}
#pragma unroll
    for (int i = 0; i < 4; i++)
#pragma unroll
        for (int j = 0; j < 4; j++) acc2[i][j] = 0ull;

    for (int k0 = 0; k0 < CIN; k0 += 16) {
        {   // X tile (64 rows x 16 k), transposed into Xs[k][row]
            int k4 = tid & 3;
            int r  = tid >> 2;
#pragma unroll
            for (int rr = 0; rr < 2; rr++) {
                int row = r + rr * 32;
                int grow = blockRow + row;
                float4 v = make_float4(0.f, 0.f, 0.f, 0.f);
                if (grow < nrows)
                    v = *(const float4*)&X[(long long)grow * CIN + k0 + k4 * 4];
                Xs[(k4 * 4 + 0) * 68 + row] = v.x;
                Xs[(k4 * 4 + 1) * 68 + row] = v.y;
                Xs[(k4 * 4 + 2) * 68 + row] = v.z;
                Xs[(k4 * 4 + 3) * 68 + row] = v.w;
            }
        }
        {   // W tile (16 k x 64 cols), duplicated pairs
            int c4 = tid & 15, kk = tid >> 4;
#pragma unroll
            for (int rr = 0; rr < 2; rr++) {
                int k = kk + rr * 8;
                float4 w = *(const float4*)&W[(long long)(k0 + k) * 64 + c4 * 4];
                Wd[k * 64 + c4 * 4 + 0] = f2u2(w.x, w.x);
                Wd[k * 64 + c4 * 4 + 1] = f2u2(w.y, w.y);
                Wd[k * 64 + c4 * 4 + 2] = f2u2(w.z, w.z);
                Wd[k * 64 + c4 * 4 + 3] = f2u2(w.w, w.w);
            }
        }
        __syncthreads();

#pragma unroll
        for (int k = 0; k < 16; k++) {
            const ull* xp = (const ull*)&Xs[k * 68 + row0];   // 4 row-pairs
            ull x0 = xp[0], x1 = xp[1], x2 = xp[2], x3 = xp[3];
            const ull* wp = &Wd[k * 64 + col0];
            ull w0 = wp[0], w1 = wp[1], w2 = wp[2], w3 = wp[3];
            ffma2(acc2[0][0], x0, w0); ffma2(acc2[0][1], x0, w1);
            ffma2(acc2[0][2], x0, w2); ffma2(acc2[0][3], x0, w3);
            ffma2(acc2[1][0], x1, w0); ffma2(acc2[1][1], x1, w1);
            ffma2(acc2[1][2], x1, w2); ffma2(acc2[1][3], x1, w3);
            ffma2(acc2[2][0], x2, w0); ffma2(acc2[2][1], x2, w1);
            ffma2(acc2[2][2], x2, w2); ffma2(acc2[2][3], x2, w3);
            ffma2(acc2[3][0], x3, w0); ffma2(acc2[3][1], x3, w1);
            ffma2(acc2[3][2], x3, w2); ffma2(acc2[3][3], x3, w3);
        }
        __syncthreads();
    }

#pragma unroll
    for (int rp = 0; rp < 4; rp++) {
        float2 c0 = u2f2(acc2[rp][0]), c1 = u2f2(acc2[rp][1]);
        float2 c2 = u2f2(acc2[rp][2]), c3 = u2f2(acc2[rp][3]);
        int re = blockRow + row0 + rp * 2;
        if (OUTW == 64) {
            if (re < nrows)
                *(float4*)&H[(long long)re * 64 + col0] = make_float4(c0.x, c1.x, c2.x, c3.x);
            if (re + 1 < nrows)
                *(float4*)&H[(long long)(re + 1) * 64 + col0] = make_float4(c0.y, c1.y, c2.y, c3.y);
        } else {  // compact 40-wide rows
            if (col0 < OUT_CH) {
                if (re < nrows)
                    *(float4*)&H[(long long)re * 40 + col0] = make_float4(c0.x, c1.x, c2.x, c3.x);
                if (re + 1 < nrows)
                    *(float4*)&H[(long long)(re + 1) * 40 + col0] = make_float4(c0.y, c1.y, c2.y, c3.y);
            }
        }
    }
}

// ---------------- gather aggregation: one warp per node, 4x unrolled ----------------
// out[d][c] = sum_e h[src_e][c]*wn_e + h[d][c]*dis[d]^2, then bias(+relu)
template <int SELOUT>
__global__ void gather64_kernel(const float* __restrict__ bias) {
    int w = (blockIdx.x * blockDim.x + threadIdx.x) >> 5;
    int lane = threadIdx.x & 31;
    if (w >= N_NODES) return;
    const float* H = g_h;
    float* O = (SELOUT == 1) ? g_a : g_b;

    const int2* cw = g_cw + g_rs[w];
    int n = g_cnt[w];
    float a0 = 0.0f, a1 = 0.0f;
    int j = 0;
    for (; j + 4 <= n; j += 4) {
        int2 e0 = cw[j], e1 = cw[j + 1], e2 = cw[j + 2], e3 = cw[j + 3];
        const float* r0 = &H[(long long)e0.x * 64];
        const float* r1 = &H[(long long)e1.x * 64];
        const float* r2 = &H[(long long)e2.x * 64];
        const float* r3 = &H[(long long)e3.x * 64];
        float t0 = __int_as_float(e0.y), t1 = __int_as_float(e1.y);
        float t2 = __int_as_float(e2.y), t3 = __int_as_float(e3.y);
        float v00 = r0[lane], v01 = r0[lane + 32];
        float v10 = r1[lane], v11 = r1[lane + 32];
        float v20 = r2[lane], v21 = r2[lane + 32];
        float v30 = r3[lane], v31 = r3[lane + 32];
        a0 = fmaf(v00, t0, a0); a1 = fmaf(v01, t0, a1);
        a0 = fmaf(v10, t1, a0); a1 = fmaf(v11, t1, a1);
        a0 = fmaf(v20, t2, a0); a1 = fmaf(v21, t2, a1);
        a0 = fmaf(v30, t3, a0); a1 = fmaf(v31, t3, a1);
    }
    for (; j < n; j++) {
        int2 e = cw[j];
        const float* r = &H[(long long)e.x * 64];
        float t = __int_as_float(e.y);
        a0 = fmaf(r[lane], t, a0);
        a1 = fmaf(r[lane + 32], t, a1);
    }
    float d = g_dis[w];
    float dsq = d * d;
    a0 = fmaf(H[(long long)w * 64 + lane],      dsq, a0);
    a1 = fmaf(H[(long long)w * 64 + lane + 32], dsq, a1);
    O[(long long)w * 64 + lane]      = fmaxf(a0 + bias[lane], 0.0f);
    O[(long long)w * 64 + lane + 32] = fmaxf(a1 + bias[lane + 32], 0.0f);
}

// final layer: gather over compact 40-wide h + bias + log_softmax
__global__ void gather40_lsm_kernel(const float* __restrict__ b3, float* __restrict__ out) {
    int w = (blockIdx.x * blockDim.x + threadIdx.x) >> 5;
    int lane = threadIdx.x & 31;
    if (w >= N_NODES) return;
    const float* H = g_h;                 // stride 40
    bool p1 = (lane < OUT_CH - 32);       // lanes 0..7

    const int2* cw = g_cw + g_rs[w];
    int n = g_cnt[w];
    float a0 = 0.0f, a1 = 0.0f;
    int j = 0;
    for (; j + 4 <= n; j += 4) {
        int2 e0 = cw[j], e1 = cw[j + 1], e2 = cw[j + 2], e3 = cw[j + 3];
        const float* r0 = &H[(long long)e0.x * 40];
        const float* r1 = &H[(long long)e1.x * 40];
        const float* r2 = &H[(long long)e2.x * 40];
        const float* r3 = &H[(long long)e3.x * 40];
        float t0 = __int_as_float(e0.y), t1 = __int_as_float(e1.y);
        float t2 = __int_as_float(e2.y), t3 = __int_as_float(e3.y);
        float v00 = r0[lane], v10 = r1[lane], v20 = r2[lane], v30 = r3[lane];
        float v01 = p1 ? r0[lane + 32] : 0.0f;
        float v11 = p1 ? r1[lane + 32] : 0.0f;
        float v21 = p1 ? r2[lane + 32] : 0.0f;
        float v31 = p1 ? r3[lane + 32] : 0.0f;
        a0 = fmaf(v00, t0, a0); a1 = fmaf(v01, t0, a1);
        a0 = fmaf(v10, t1, a0); a1 = fmaf(v11, t1, a1);
        a0 = fmaf(v20, t2, a0); a1 = fmaf(v21, t2, a1);
        a0 = fmaf(v30, t3, a0); a1 = fmaf(v31, t3, a1);
    }
    for (; j < n; j++) {
        int2 e = cw[j];
        const float* r = &H[(long long)e.x * 40];
        float t = __int_as_float(e.y);
        a0 = fmaf(r[lane], t, a0);
        if (p1) a1 = fmaf(r[lane + 32], t, a1);
    }
    float d = g_dis[w];
    float dsq = d * d;
    a0 = fmaf(H[(long long)w * 40 + lane], dsq, a0);
    if (p1) a1 = fmaf(H[(long long)w * 40 + lane + 32], dsq, a1);

    float v0 = a0 + b3[lane];
    float v1 = p1 ? (a1 + b3[lane + 32]) : -1e30f;

    float m = fmaxf(v0, v1);
#pragma unroll
    for (int o = 16; o; o >>= 1) m = fmaxf(m, __shfl_xor_sync(0xffffffffu, m, o));
    float s = expf(v0 - m) + (p1 ? expf(v1 - m) : 0.0f);
#pragma unroll
    for (int o = 16; o; o >>= 1) s += __shfl_xor_sync(0xffffffffu, s, o);
    float ls = logf(s);

    float* r = out + (long long)w * OUT_CH;
    r[lane] = v0 - m - ls;
    if (p1) r[lane + 32] = v1 - m - ls;
}

// ---------------- launch ----------------
extern "C" void kernel_launch(void* const* d_in, const int* in_sizes, int n_in,
                              void* d_out, int out_size) {
    const float* x  = (const float*)d_in[0];
    const int*   ei = (const int*)d_in[1];     // int32 (JAX x64 disabled)
    const float* W1 = (const float*)d_in[2];
    const float* b1 = (const float*)d_in[3];
    const float* W2 = (const float*)d_in[4];
    const float* b2 = (const float*)d_in[5];
    const float* W3 = (const float*)d_in[6];
    const float* b3 = (const float*)d_in[7];
    float* out = (float*)d_out;

    const int T = 256;

    // ---- CSR / norm prep ----
    cnt_zero_kernel<<<cdiv_i(N_NODES, T), T>>>();
    deg_count_kernel<<<cdiv_i(N_EDGES, T), T>>>(ei);
    dis_kernel<<<cdiv_i(N_NODES, T), T>>>();
    scan_block_kernel<<<SCAN_NB, SCAN_B>>>();
    scan_sums_kernel<<<1, 32>>>();
    scan_add_kernel<<<SCAN_NB, SCAN_B>>>();
    fill_csr_kernel<<<cdiv_i(N_EDGES, T), T>>>(ei);
    padw3_kernel<<<cdiv_i(64 * 64, T), T>>>(W3);

    const int gemm_blocks   = cdiv_i(N_NODES, 64);
    const int gather_blocks = cdiv_i((long long)N_NODES * 32, T);

    // ---- layer 1: 128 -> 64, relu ----
    gemm64_kernel<IN_CH, 0, 0, 64><<<gemm_blocks, 128>>>(x, W1, N_NODES);
    gather64_kernel<1><<<gather_blocks, T>>>(b1);

    // ---- layer 2: 64 -> 64, relu ----
    gemm64_kernel<HID_CH, 1, 0, 64><<<gemm_blocks, 128>>>(nullptr, W2, N_NODES);
    gather64_kernel<2><<<gather_blocks, T>>>(b2);

    // ---- layer 3: 64 -> 40 (compact rows), bias + log_softmax fused ----
    gemm64_kernel<HID_CH, 2, 1, 40><<<gemm_blocks, 128>>>(nullptr, nullptr, N_NODES);
    gather40_lsm_kernel<<<gather_blocks, T>>>(b3, out);
}